// round 12
// baseline (speedup 1.0000x reference)
#include <cuda_runtime.h>
#include <cuda_bf16.h>
#include <math.h>
#include <stdint.h>

// ---------------------------------------------------------------------------
// BSPLoss: out = lam1 + 0.5*(lam2+lam3), lam_i = top eigenvalue of F_i^T F_i.
// Gram (4-way K-split, fp32 partials) + 9 Frobenius-normalized symmetric
// squarings carried in bf16.  k=1 fuses the Gram partial-sum (fp32 loader);
// k>=2 uses a 4-stage cp.async pipeline (bf16 tiles copied untouched) with
// double-buffered ldmatrix fragments.  All GEMMs mma.sync bf16, fp32 accum.
// ---------------------------------------------------------------------------

#define DIM    1024
#define NROWS  8192
#define M_SQ   9
#define NTILE  36
#define KSPLIT 4
#define PSTR   ((size_t)3 * DIM * DIM)

// Gram kernel (KC=16, 128 threads)
#define KCG     16
#define GREGB   4096
#define GSTAGEB (2 * GREGB)
#define GSMEMB  (2 * GSTAGEB + 1024)

// Squaring kernels (KC=32, 256 threads, tile 128x128, warps 64x32)
#define KCS     32
#define SREGB   (KCS * 256)          // 8 KB per operand region
#define SSTAGEB (2 * SREGB)          // 16 KB per stage
#define SSMEMB  (2 * SSTAGEB + 1024) // fused kernel (2-stage)
#define NSTG    4
#define CSMEMB  (NSTG * SSTAGEB)     // cp.async kernel (4-stage, 64 KB)

__device__ __align__(16) float          g_part[KSPLIT][3][DIM * DIM];
__device__ __align__(16) __nv_bfloat16  g_hbuf[2][3][DIM * DIM];
__device__ double g_frob[3];
__device__ float  g_inv[3];
__device__ double g_logacc[3];
__device__ int    g_ctr[3];

__global__ void init_kernel() {
    int i = threadIdx.x;
    if (i < 3) { g_frob[i] = 0.0; g_inv[i] = 1.0f; g_logacc[i] = 0.0; g_ctr[i] = 0; }
}

__device__ __forceinline__ uint32_t smem_u32(const void* p) {
    uint32_t a;
    asm("{ .reg .u64 t; cvta.to.shared.u64 t, %1; cvt.u32.u64 %0, t; }"
        : "=r"(a) : "l"(p));
    return a;
}

__device__ __forceinline__ void ldsm4t(uint32_t* r, uint32_t addr) {
    asm volatile("ldmatrix.sync.aligned.m8n8.x4.trans.shared.b16 {%0,%1,%2,%3}, [%4];"
                 : "=r"(r[0]), "=r"(r[1]), "=r"(r[2]), "=r"(r[3]) : "r"(addr));
}

__device__ __forceinline__ void mma16816(float* c, const uint32_t* a,
                                         uint32_t b0, uint32_t b1) {
    asm volatile("mma.sync.aligned.m16n8k16.row.col.f32.bf16.bf16.f32 "
                 "{%0,%1,%2,%3}, {%4,%5,%6,%7}, {%8,%9}, {%0,%1,%2,%3};"
                 : "+f"(c[0]), "+f"(c[1]), "+f"(c[2]), "+f"(c[3])
                 : "r"(a[0]), "r"(a[1]), "r"(a[2]), "r"(a[3]), "r"(b0), "r"(b1));
}

__device__ __forceinline__ uint32_t swz256(uint32_t base, int row, int chunk) {
    return base + row * 256 + ((chunk ^ (row & 7)) << 4);
}

__device__ __forceinline__ void cvt_h(float4 v, uint2& hi) {
    __nv_bfloat162 h0 = __floats2bfloat162_rn(v.x, v.y);
    __nv_bfloat162 h1 = __floats2bfloat162_rn(v.z, v.w);
    hi.x = *(uint32_t*)&h0; hi.y = *(uint32_t*)&h1;
}

__device__ __forceinline__ float4 ldp4(const float* p) {
    float4 v  = *(const float4*)p;
    float4 w1 = *(const float4*)(p + PSTR);
    float4 w2 = *(const float4*)(p + 2 * PSTR);
    float4 w3 = *(const float4*)(p + 3 * PSTR);
    v.x = (v.x + w1.x) + (w2.x + w3.x);
    v.y = (v.y + w1.y) + (w2.y + w3.y);
    v.z = (v.z + w1.z) + (w2.z + w3.z);
    v.w = (v.w + w1.w) + (w2.w + w3.w);
    return v;
}

#define CP_ASYNC16(dst, src) \
    asm volatile("cp.async.ca.shared.global [%0], [%1], 16;" \
                 :: "r"(dst), "l"(src) : "memory")
#define CP_COMMIT() asm volatile("cp.async.commit_group;" ::: "memory")
#define CP_WAIT2()  asm volatile("cp.async.wait_group 2;" ::: "memory")

// ============ Gram kernel (proven): 128 thr, KC=16, K-split grid ============
__device__ __forceinline__ void gram_store_stage(char* bufp, const float4* rI,
                                                 const float4* rJ, int row, int c4) {
#pragma unroll
    for (int it = 0; it < 4; it++) {
        const int col4 = c4 + it * 8;
        const int chunk = col4 >> 1;
        const uint32_t off = (uint32_t)(row * 256) +
                             ((chunk ^ (row & 7)) << 4) + ((col4 & 1) * 8);
        uint2 hi;
        cvt_h(rI[it], hi);
        *(uint2*)(bufp + off) = hi;
        cvt_h(rJ[it], hi);
        *(uint2*)(bufp + GREGB + off) = hi;
    }
}

__device__ __forceinline__ void gram_compute(uint32_t u, float acc[4][8][4],
                                             int wm, int wn, int g, int tr) {
    const uint32_t IHI = u, JHI = u + GREGB;
    const int rowA = ((g & 2) ? 8 : 0) + tr;
    const int rowB = ((g & 1) ? 8 : 0) + tr;
    uint32_t ax[4][4], bh[4][4];
#pragma unroll
    for (int mi = 0; mi < 4; mi++)
        ldsm4t(ax[mi], swz256(IHI, rowA, (wm >> 3) + mi * 2 + (g & 1)));
#pragma unroll
    for (int nb = 0; nb < 4; nb++)
        ldsm4t(bh[nb], swz256(JHI, rowB, (wn >> 3) + nb * 2 + (g >> 1)));
#pragma unroll
    for (int mi = 0; mi < 4; mi++)
#pragma unroll
        for (int nj = 0; nj < 8; nj++)
            mma16816(acc[mi][nj], ax[mi],
                     bh[nj >> 1][(nj & 1) * 2], bh[nj >> 1][(nj & 1) * 2 + 1]);
}

__global__ void __launch_bounds__(128)
ata_mma_kernel(const float* __restrict__ a0, const float* __restrict__ a1,
               const float* __restrict__ a2, int Kper)
{
    extern __shared__ __align__(16) char dynsmem[];

    const int z = blockIdx.z;
    const float* A = (z == 0) ? a0 : ((z == 1) ? a1 : a2);
    float* C = g_part[blockIdx.y][z];

    int t = blockIdx.x, bi = 0;
    while (t >= 8 - bi) { t -= 8 - bi; bi++; }
    const int bj = bi + t;
    const int i0 = bi * 128, j0 = bj * 128;

    const int tid = threadIdx.x;
    const int w = tid >> 5, l = tid & 31;
    const int wm = (w >> 1) * 64, wn = (w & 1) * 64;
    const int tr = l & 7, g = l >> 3;
    const int row = tid >> 3, c4 = tid & 7;

    const uint32_t sb = smem_u32(dynsmem);
    const uint32_t ab = (sb + 1023u) & ~1023u;
    char* aptr = dynsmem + (ab - sb);

    float acc[4][8][4];
#pragma unroll
    for (int mi = 0; mi < 4; mi++)
#pragma unroll
        for (int nj = 0; nj < 8; nj++)
#pragma unroll
            for (int q = 0; q < 4; q++) acc[mi][nj][q] = 0.0f;

    const size_t kbase = (size_t)blockIdx.y * Kper;
    const float* pI = A + kbase * DIM + i0 + c4 * 4;
    const float* pJ = A + kbase * DIM + j0 + c4 * 4;

    const int S = Kper / KCG;
    float4 rI[4], rJ[4];
    {
        const size_t b0 = (size_t)row * DIM;
#pragma unroll
        for (int it = 0; it < 4; it++) {
            rI[it] = *(const float4*)(pI + b0 + it * 32);
            rJ[it] = *(const float4*)(pJ + b0 + it * 32);
        }
    }
    gram_store_stage(aptr, rI, rJ, row, c4);
    {
        const size_t b1 = (size_t)(KCG + row) * DIM;
#pragma unroll
        for (int it = 0; it < 4; it++) {
            rI[it] = *(const float4*)(pI + b1 + it * 32);
            rJ[it] = *(const float4*)(pJ + b1 + it * 32);
        }
    }
    __syncthreads();

    for (int s = 0; s < S; s++) {
        const int b = s & 1;
        if (s + 1 < S)
            gram_store_stage(aptr + (b ^ 1) * GSTAGEB, rI, rJ, row, c4);
        if (s + 2 < S) {
            const size_t bb = (size_t)((s + 2) * KCG + row) * DIM;
#pragma unroll
            for (int it = 0; it < 4; it++) {
                rI[it] = *(const float4*)(pI + bb + it * 32);
                rJ[it] = *(const float4*)(pJ + bb + it * 32);
            }
        }
        gram_compute(ab + b * GSTAGEB, acc, wm, wn, g, tr);
        __syncthreads();
    }

    const int r  = l >> 2;
    const int c2 = 2 * (l & 3);
#pragma unroll
    for (int mi = 0; mi < 4; mi++) {
#pragma unroll
        for (int nj = 0; nj < 8; nj++) {
            float* a = acc[mi][nj];
            const int gr = i0 + wm + mi * 16 + r;
            const int gc = j0 + wn + nj * 8 + c2;
            *(float2*)&C[(size_t)gr * DIM + gc]       = make_float2(a[0], a[1]);
            *(float2*)&C[(size_t)(gr + 8) * DIM + gc] = make_float2(a[2], a[3]);
            if (bi != bj) {
                C[(size_t)gc * DIM + gr]           = a[0];
                C[(size_t)(gc + 1) * DIM + gr]     = a[1];
                C[(size_t)gc * DIM + gr + 8]       = a[2];
                C[(size_t)(gc + 1) * DIM + gr + 8] = a[3];
            }
        }
    }
}

// ---- shared epilogue for squaring kernels ----
__device__ __forceinline__ void sq_epilogue(float acc[4][4][4], int bi, int bj,
                                            int i0, int j0, int wm, int wn,
                                            int tid, int w, int l, float s2,
                                            int do_write, double wfin,
                                            __nv_bfloat16* Cb, int z,
                                            float* sh_wsum)
{
    const float w2 = (bi == bj) ? 1.0f : 2.0f;
    float fr = 0.0f;
    const int r  = l >> 2;
    const int c2 = 2 * (l & 3);
#pragma unroll
    for (int mi = 0; mi < 4; mi++) {
#pragma unroll
        for (int nj = 0; nj < 4; nj++) {
            float* a = acc[mi][nj];
#pragma unroll
            for (int q = 0; q < 4; q++) {
                a[q] *= s2;
                fr = fmaf(w2 * a[q], a[q], fr);
            }
            if (do_write) {
                const int gr = i0 + wm + mi * 16 + r;
                const int gc = j0 + wn + nj * 8 + c2;
                __nv_bfloat162 h01 = __floats2bfloat162_rn(a[0], a[1]);
                __nv_bfloat162 h23 = __floats2bfloat162_rn(a[2], a[3]);
                *reinterpret_cast<__nv_bfloat162*>(&Cb[(size_t)gr * DIM + gc]) = h01;
                *reinterpret_cast<__nv_bfloat162*>(&Cb[(size_t)(gr + 8) * DIM + gc]) = h23;
                if (bi != bj) {
                    Cb[(size_t)gc * DIM + gr]           = h01.x;
                    Cb[(size_t)(gc + 1) * DIM + gr]     = h01.y;
                    Cb[(size_t)gc * DIM + gr + 8]       = h23.x;
                    Cb[(size_t)(gc + 1) * DIM + gr + 8] = h23.y;
                }
            }
        }
    }
#pragma unroll
    for (int o = 16; o > 0; o >>= 1)
        fr += __shfl_xor_sync(0xffffffffu, fr, o);
    if (l == 0) sh_wsum[w] = fr;
    __syncthreads();
    if (tid == 0) {
        double tot = 0.0;
        for (int i = 0; i < 8; i++) tot += (double)sh_wsum[i];
        atomicAdd(&g_frob[z], tot);
        __threadfence();
        int tk = atomicAdd(&g_ctr[z], 1);
        if (tk == NTILE - 1) {
            g_ctr[z] = 0;
            __threadfence();
            double c = sqrt(g_frob[z]);
            g_inv[z] = (float)(1.0 / c);
            g_logacc[z] += log2(c) * wfin;
            g_frob[z] = 0.0;
        }
    }
}

// Fragment loads for one k16 step (warp tile 64x32).
__device__ __forceinline__ void load_frags(uint32_t u, int kk, int wm, int wn,
                                           int g, int tr,
                                           uint32_t ah[4][4], uint32_t bh[2][4]) {
    const int rowB = kk + ((g & 1) ? 8 : 0) + tr;
#pragma unroll
    for (int nb = 0; nb < 2; nb++)
        ldsm4t(bh[nb], swz256(u + SREGB, rowB, (wn >> 3) + nb * 2 + (g >> 1)));
    const int rowA = kk + ((g & 2) ? 8 : 0) + tr;
#pragma unroll
    for (int mi = 0; mi < 4; mi++)
        ldsm4t(ah[mi], swz256(u, rowA, (wm >> 3) + mi * 2 + (g & 1)));
}

__device__ __forceinline__ void mma_step(float acc[4][4][4],
                                         uint32_t ah[4][4], uint32_t bh[2][4]) {
#pragma unroll
    for (int mi = 0; mi < 4; mi++)
#pragma unroll
        for (int nj = 0; nj < 4; nj++)
            mma16816(acc[mi][nj], ah[mi],
                     bh[nj >> 1][(nj & 1) * 2], bh[nj >> 1][(nj & 1) * 2 + 1]);
}

// ===== Fused k=1 squaring (fp32 partial-sum loader, proven R11 path) ========
__global__ void __launch_bounds__(256, 1)
sq_fused_kernel(int dst_sel, double wfin)
{
    extern __shared__ __align__(16) char dynsmem[];
    __shared__ float sh_wsum[8];

    const int z = blockIdx.z;
    const float* Af = g_part[0][z];
    __nv_bfloat16* Cb = g_hbuf[dst_sel][z];

    int t = blockIdx.x, bi = 0;
    while (t >= 8 - bi) { t -= 8 - bi; bi++; }
    const int bj = bi + t;
    const int i0 = bi * 128, j0 = bj * 128;

    const int tid = threadIdx.x;
    const int w = tid >> 5, l = tid & 31;
    const int wm = (w >> 2) * 64;
    const int wn = (w & 3) * 32;
    const int tr = l & 7, g = l >> 3;

    const float sv = g_inv[z];
    const float s2 = sv * sv;

    const uint32_t sb = smem_u32(dynsmem);
    const uint32_t ab = (sb + 1023u) & ~1023u;
    char* aptr = dynsmem + (ab - sb);

    float acc[4][4][4];
#pragma unroll
    for (int mi = 0; mi < 4; mi++)
#pragma unroll
        for (int nj = 0; nj < 4; nj++)
#pragma unroll
            for (int q = 0; q < 4; q++) acc[mi][nj][q] = 0.0f;

    const float* AIf = Af + i0 + 4 * l;
    const float* AJf = Af + j0 + 4 * l;
    const int lrow = w * 4;
    const int chunk = l >> 1;
    const int boff  = (l & 1) << 3;

    const int S = DIM / KCS;
    uint2 sI[4], sJ[4];

    auto loadf = [&](int kbase) {
#pragma unroll
        for (int rr = 0; rr < 4; rr++) {
            float4 v = ldp4(AIf + (size_t)(kbase + lrow + rr) * DIM);
            cvt_h(v, sI[rr]);
            v = ldp4(AJf + (size_t)(kbase + lrow + rr) * DIM);
            cvt_h(v, sJ[rr]);
        }
    };
    auto storef = [&](char* bufp) {
#pragma unroll
        for (int rr = 0; rr < 4; rr++) {
            const int k = lrow + rr;
            const uint32_t off = (uint32_t)(k * 256) + ((chunk ^ (k & 7)) << 4) + boff;
            *(uint2*)(bufp + off)         = sI[rr];
            *(uint2*)(bufp + SREGB + off) = sJ[rr];
        }
    };

    loadf(0);
    storef(aptr);
    loadf(KCS);
    __syncthreads();

    for (int s = 0; s < S; s++) {
        const int b = s & 1;
        if (s + 1 < S) storef(aptr + (b ^ 1) * SSTAGEB);
        if (s + 2 < S) loadf((s + 2) * KCS);
        const uint32_t u = ab + b * SSTAGEB;
        uint32_t ah[2][4][4], bh[2][2][4];
        load_frags(u, 0, wm, wn, g, tr, ah[0], bh[0]);
#pragma unroll
        for (int kk = 0; kk < KCS; kk += 16) {
            const int cu = (kk >> 4) & 1;
            if (kk + 16 < KCS)
                load_frags(u, kk + 16, wm, wn, g, tr, ah[cu ^ 1], bh[cu ^ 1]);
            mma_step(acc, ah[cu], bh[cu]);
        }
        __syncthreads();
    }

    sq_epilogue(acc, bi, bj, i0, j0, wm, wn, tid, w, l, s2, 1, wfin, Cb, z, sh_wsum);
}

// ===== k>=2 squaring: 4-stage cp.async pipeline, bf16 chain =================
__global__ void __launch_bounds__(256, 1)
sq_cp_kernel(int src_sel, int dst_sel, int do_write, double wfin)
{
    extern __shared__ __align__(16) char dynsmem[];
    __shared__ float sh_wsum[8];

    const int z = blockIdx.z;
    const __nv_bfloat16* Ab = g_hbuf[src_sel][z];
    __nv_bfloat16* Cb = g_hbuf[dst_sel][z];

    int t = blockIdx.x, bi = 0;
    while (t >= 8 - bi) { t -= 8 - bi; bi++; }
    const int bj = bi + t;
    const int i0 = bi * 128, j0 = bj * 128;

    const int tid = threadIdx.x;
    const int w = tid >> 5, l = tid & 31;
    const int wm = (w >> 2) * 64;
    const int wn = (w & 3) * 32;
    const int tr = l & 7, g = l >> 3;
    const int row = tid >> 3;              // 0..31 k-row
    const int cb  = (tid & 7) * 2;         // chunk base (2 chunks of 16B)

    const float sv = g_inv[z];
    const float s2 = sv * sv;

    const uint32_t sb = smem_u32(dynsmem); // 16B aligned is enough (swizzle-local)

    float acc[4][4][4];
#pragma unroll
    for (int mi = 0; mi < 4; mi++)
#pragma unroll
        for (int nj = 0; nj < 4; nj++)
#pragma unroll
            for (int q = 0; q < 4; q++) acc[mi][nj][q] = 0.0f;

    const __nv_bfloat16* baseI = Ab + i0;
    const __nv_bfloat16* baseJ = Ab + j0;

    const int S = DIM / KCS;   // 32 stages

    auto issue_stage = [&](int s) {
        const uint32_t bufb = sb + (uint32_t)(s & (NSTG - 1)) * SSTAGEB;
        const size_t krow = (size_t)(s * KCS + row) * DIM;
#pragma unroll
        for (int cc = 0; cc < 2; cc++) {
            const int ch = cb + cc;
            const uint32_t off = (uint32_t)(row * 256) + ((ch ^ (row & 7)) << 4);
            CP_ASYNC16(bufb + off,         baseI + krow + ch * 8);
            CP_ASYNC16(bufb + SREGB + off, baseJ + krow + ch * 8);
        }
    };

    // prologue: fill 3 stages
    issue_stage(0); CP_COMMIT();
    issue_stage(1); CP_COMMIT();
    issue_stage(2); CP_COMMIT();

    for (int s = 0; s < S; s++) {
        CP_WAIT2();
        __syncthreads();
        if (s + 3 < S) issue_stage(s + 3);
        CP_COMMIT();
        const uint32_t u = sb + (uint32_t)(s & (NSTG - 1)) * SSTAGEB;
        uint32_t ah[2][4][4], bh[2][2][4];
        load_frags(u, 0, wm, wn, g, tr, ah[0], bh[0]);
#pragma unroll
        for (int kk = 0; kk < KCS; kk += 16) {
            const int cu = (kk >> 4) & 1;
            if (kk + 16 < KCS)
                load_frags(u, kk + 16, wm, wn, g, tr, ah[cu ^ 1], bh[cu ^ 1]);
            mma_step(acc, ah[cu], bh[cu]);
        }
    }
    __syncthreads();

    sq_epilogue(acc, bi, bj, i0, j0, wm, wn, tid, w, l, s2, do_write, wfin,
                Cb, z, sh_wsum);
}

__global__ void out_kernel(float* __restrict__ out) {
    double l0 = exp2(g_logacc[0]);
    double l1 = exp2(g_logacc[1]);
    double l2 = exp2(g_logacc[2]);
    out[0] = (float)(l0 + 0.5 * (l1 + l2));
}

extern "C" void kernel_launch(void* const* d_in, const int* in_sizes, int n_in,
                              void* d_out, int out_size)
{
    const float* f1 = (const float*)d_in[0];
    const float* f2 = (const float*)d_in[1];
    const float* f3 = (const float*)d_in[2];
    (void)in_sizes; (void)n_in; (void)out_size;

    static int configured = 0;
    if (!configured) {
        cudaFuncSetAttribute(ata_mma_kernel,
                             cudaFuncAttributeMaxDynamicSharedMemorySize, GSMEMB);
        cudaFuncSetAttribute(sq_fused_kernel,
                             cudaFuncAttributeMaxDynamicSharedMemorySize, SSMEMB);
        cudaFuncSetAttribute(sq_cp_kernel,
                             cudaFuncAttributeMaxDynamicSharedMemorySize, CSMEMB);
        configured = 1;
    }

    init_kernel<<<1, 4>>>();

    // Gram: 4-way K-split into fp32 partial planes (single bf16 product)
    ata_mma_kernel<<<dim3(NTILE, KSPLIT, 3), 128, GSMEMB>>>(
        f1, f2, f3, NROWS / KSPLIT);

    // k=1: fused partial-sum loader (fp32), writes bf16 -> hbuf[0]
    sq_fused_kernel<<<dim3(NTILE, 1, 3), 256, SSMEMB>>>(0, exp2(-1.0));
    int cur = 0;
    for (int k = 2; k <= M_SQ; k++) {
        int dst = 1 - cur;
        int dow = (k < M_SQ) ? 1 : 0;
        sq_cp_kernel<<<dim3(NTILE, 1, 3), 256, CSMEMB>>>(
            cur, dst, dow, exp2(-(double)k));
        cur = dst;
    }
    out_kernel<<<1, 1>>>((float*)d_out);
}

// round 13
// speedup vs baseline: 1.0736x; 1.0736x over previous
#include <cuda_runtime.h>
#include <cuda_bf16.h>
#include <math.h>
#include <stdint.h>

// ---------------------------------------------------------------------------
// BSPLoss: out = lam1 + 0.5*(lam2+lam3), lam_i = top eigenvalue of F_i^T F_i.
// Pipeline: F -> bf16 (pre-pass) ; Gram via cp.async bf16 GEMM (4-way K-split,
// fp32 partials) ; k=1 squaring fuses partial-sum (fp32 loader, R11-proven) ;
// k=2..9 squarings via cp.async bf16 GEMM.  Frobenius-normalized chain,
// log2(lam) = sum 2^-k log2(c_k).  All GEMMs mma.sync bf16, fp32 accum.
// ---------------------------------------------------------------------------

#define DIM    1024
#define NROWS  8192
#define M_SQ   9
#define NTILE  36
#define KSPLIT 4
#define PSTR   ((size_t)3 * DIM * DIM)

#define KCS     32
#define SREGB   (KCS * 256)          // 8 KB per operand region
#define SSTAGEB (2 * SREGB)          // 16 KB per stage
#define SSMEMB  (2 * SSTAGEB + 1024) // fused kernel (2-stage + align pad)
#define NSTG    4
#define CSMEMB  (NSTG * SSTAGEB)     // cp.async kernels (4-stage, 64 KB)

__device__ __align__(16) float          g_part[KSPLIT][3][DIM * DIM];
__device__ __align__(16) __nv_bfloat16  g_hbuf[2][3][DIM * DIM];
__device__ __align__(16) __nv_bfloat16  g_fbuf[3][NROWS * DIM];
__device__ double g_frob[3];
__device__ float  g_inv[3];
__device__ double g_logacc[3];
__device__ int    g_ctr[3];

__global__ void init_kernel() {
    int i = threadIdx.x;
    if (i < 3) { g_frob[i] = 0.0; g_inv[i] = 1.0f; g_logacc[i] = 0.0; g_ctr[i] = 0; }
}

__device__ __forceinline__ uint32_t smem_u32(const void* p) {
    uint32_t a;
    asm("{ .reg .u64 t; cvta.to.shared.u64 t, %1; cvt.u32.u64 %0, t; }"
        : "=r"(a) : "l"(p));
    return a;
}

__device__ __forceinline__ void ldsm4t(uint32_t* r, uint32_t addr) {
    asm volatile("ldmatrix.sync.aligned.m8n8.x4.trans.shared.b16 {%0,%1,%2,%3}, [%4];"
                 : "=r"(r[0]), "=r"(r[1]), "=r"(r[2]), "=r"(r[3]) : "r"(addr));
}

__device__ __forceinline__ void mma16816(float* c, const uint32_t* a,
                                         uint32_t b0, uint32_t b1) {
    asm volatile("mma.sync.aligned.m16n8k16.row.col.f32.bf16.bf16.f32 "
                 "{%0,%1,%2,%3}, {%4,%5,%6,%7}, {%8,%9}, {%0,%1,%2,%3};"
                 : "+f"(c[0]), "+f"(c[1]), "+f"(c[2]), "+f"(c[3])
                 : "r"(a[0]), "r"(a[1]), "r"(a[2]), "r"(a[3]), "r"(b0), "r"(b1));
}

__device__ __forceinline__ uint32_t swz256(uint32_t base, int row, int chunk) {
    return base + row * 256 + ((chunk ^ (row & 7)) << 4);
}

__device__ __forceinline__ void cvt_h(float4 v, uint2& hi) {
    __nv_bfloat162 h0 = __floats2bfloat162_rn(v.x, v.y);
    __nv_bfloat162 h1 = __floats2bfloat162_rn(v.z, v.w);
    hi.x = *(uint32_t*)&h0; hi.y = *(uint32_t*)&h1;
}

__device__ __forceinline__ float4 ldp4(const float* p) {
    float4 v  = *(const float4*)p;
    float4 w1 = *(const float4*)(p + PSTR);
    float4 w2 = *(const float4*)(p + 2 * PSTR);
    float4 w3 = *(const float4*)(p + 3 * PSTR);
    v.x = (v.x + w1.x) + (w2.x + w3.x);
    v.y = (v.y + w1.y) + (w2.y + w3.y);
    v.z = (v.z + w1.z) + (w2.z + w3.z);
    v.w = (v.w + w1.w) + (w2.w + w3.w);
    return v;
}

#define CP_ASYNC16(dst, src) \
    asm volatile("cp.async.ca.shared.global [%0], [%1], 16;" \
                 :: "r"(dst), "l"(src) : "memory")
#define CP_COMMIT() asm volatile("cp.async.commit_group;" ::: "memory")
#define CP_WAIT2()  asm volatile("cp.async.wait_group 2;" ::: "memory")

// ============ fp32 -> bf16 conversion pre-pass ============
__global__ void __launch_bounds__(256)
cvt_kernel(const float* __restrict__ a0, const float* __restrict__ a1,
           const float* __restrict__ a2)
{
    const int z = blockIdx.y;
    const float* A = (z == 0) ? a0 : ((z == 1) ? a1 : a2);
    __nv_bfloat16* D = g_fbuf[z];
    const int n = NROWS * DIM / 4;
    for (int i = blockIdx.x * blockDim.x + threadIdx.x; i < n;
         i += gridDim.x * blockDim.x) {
        float4 v = *(const float4*)(A + (size_t)i * 4);
        uint2 h;
        cvt_h(v, h);
        *(uint2*)(D + (size_t)i * 4) = h;
    }
}

// ---- fragment helpers (warp tile 64x32) ----
__device__ __forceinline__ void load_frags(uint32_t u, int kk, int wm, int wn,
                                           int g, int tr,
                                           uint32_t ah[4][4], uint32_t bh[2][4]) {
    const int rowB = kk + ((g & 1) ? 8 : 0) + tr;
#pragma unroll
    for (int nb = 0; nb < 2; nb++)
        ldsm4t(bh[nb], swz256(u + SREGB, rowB, (wn >> 3) + nb * 2 + (g >> 1)));
    const int rowA = kk + ((g & 2) ? 8 : 0) + tr;
#pragma unroll
    for (int mi = 0; mi < 4; mi++)
        ldsm4t(ah[mi], swz256(u, rowA, (wm >> 3) + mi * 2 + (g & 1)));
}

__device__ __forceinline__ void mma_step(float acc[4][4][4],
                                         uint32_t ah[4][4], uint32_t bh[2][4]) {
#pragma unroll
    for (int mi = 0; mi < 4; mi++)
#pragma unroll
        for (int nj = 0; nj < 4; nj++)
            mma16816(acc[mi][nj], ah[mi],
                     bh[nj >> 1][(nj & 1) * 2], bh[nj >> 1][(nj & 1) * 2 + 1]);
}

// ============ Gram kernel: cp.async bf16, tile 128x128, K-split grid ========
__global__ void __launch_bounds__(256, 1)
gram_cp_kernel()
{
    extern __shared__ __align__(16) char dynsmem[];

    const int z  = blockIdx.z;
    const int ky = blockIdx.y;
    const __nv_bfloat16* Ab = g_fbuf[z];
    float* C = g_part[ky][z];

    int t = blockIdx.x, bi = 0;
    while (t >= 8 - bi) { t -= 8 - bi; bi++; }
    const int bj = bi + t;
    const int i0 = bi * 128, j0 = bj * 128;

    const int tid = threadIdx.x;
    const int w = tid >> 5, l = tid & 31;
    const int wm = (w >> 2) * 64;
    const int wn = (w & 3) * 32;
    const int tr = l & 7, g = l >> 3;
    const int row = tid >> 3;
    const int cb  = (tid & 7) * 2;

    const uint32_t sb = smem_u32(dynsmem);

    float acc[4][4][4];
#pragma unroll
    for (int mi = 0; mi < 4; mi++)
#pragma unroll
        for (int nj = 0; nj < 4; nj++)
#pragma unroll
            for (int q = 0; q < 4; q++) acc[mi][nj][q] = 0.0f;

    const __nv_bfloat16* baseI = Ab + i0;
    const __nv_bfloat16* baseJ = Ab + j0;
    const int kbase = ky * (NROWS / KSPLIT);

    const int S = (NROWS / KSPLIT) / KCS;   // 64 stages

    auto issue_stage = [&](int s) {
        const uint32_t bufb = sb + (uint32_t)(s & (NSTG - 1)) * SSTAGEB;
        const size_t krow = (size_t)(kbase + s * KCS + row) * DIM;
#pragma unroll
        for (int cc = 0; cc < 2; cc++) {
            const int ch = cb + cc;
            const uint32_t off = (uint32_t)(row * 256) + ((ch ^ (row & 7)) << 4);
            CP_ASYNC16(bufb + off,         baseI + krow + ch * 8);
            CP_ASYNC16(bufb + SREGB + off, baseJ + krow + ch * 8);
        }
    };

    issue_stage(0); CP_COMMIT();
    issue_stage(1); CP_COMMIT();
    issue_stage(2); CP_COMMIT();

    for (int s = 0; s < S; s++) {
        CP_WAIT2();
        __syncthreads();
        if (s + 3 < S) issue_stage(s + 3);
        CP_COMMIT();
        const uint32_t u = sb + (uint32_t)(s & (NSTG - 1)) * SSTAGEB;
        uint32_t ah[2][4][4], bh[2][2][4];
        load_frags(u, 0, wm, wn, g, tr, ah[0], bh[0]);
#pragma unroll
        for (int kk = 0; kk < KCS; kk += 16) {
            const int cu = (kk >> 4) & 1;
            if (kk + 16 < KCS)
                load_frags(u, kk + 16, wm, wn, g, tr, ah[cu ^ 1], bh[cu ^ 1]);
            mma_step(acc, ah[cu], bh[cu]);
        }
    }

    // epilogue: fp32 partial store + mirror
    const int r  = l >> 2;
    const int c2 = 2 * (l & 3);
#pragma unroll
    for (int mi = 0; mi < 4; mi++) {
#pragma unroll
        for (int nj = 0; nj < 4; nj++) {
            float* a = acc[mi][nj];
            const int gr = i0 + wm + mi * 16 + r;
            const int gc = j0 + wn + nj * 8 + c2;
            *(float2*)&C[(size_t)gr * DIM + gc]       = make_float2(a[0], a[1]);
            *(float2*)&C[(size_t)(gr + 8) * DIM + gc] = make_float2(a[2], a[3]);
            if (bi != bj) {
                C[(size_t)gc * DIM + gr]           = a[0];
                C[(size_t)(gc + 1) * DIM + gr]     = a[1];
                C[(size_t)gc * DIM + gr + 8]       = a[2];
                C[(size_t)(gc + 1) * DIM + gr + 8] = a[3];
            }
        }
    }
}

// ---- shared epilogue for squaring kernels ----
__device__ __forceinline__ void sq_epilogue(float acc[4][4][4], int bi, int bj,
                                            int i0, int j0, int wm, int wn,
                                            int tid, int w, int l, float s2,
                                            int do_write, double wfin,
                                            __nv_bfloat16* Cb, int z,
                                            float* sh_wsum)
{
    const float w2 = (bi == bj) ? 1.0f : 2.0f;
    float fr = 0.0f;
    const int r  = l >> 2;
    const int c2 = 2 * (l & 3);
#pragma unroll
    for (int mi = 0; mi < 4; mi++) {
#pragma unroll
        for (int nj = 0; nj < 4; nj++) {
            float* a = acc[mi][nj];
#pragma unroll
            for (int q = 0; q < 4; q++) {
                a[q] *= s2;
                fr = fmaf(w2 * a[q], a[q], fr);
            }
            if (do_write) {
                const int gr = i0 + wm + mi * 16 + r;
                const int gc = j0 + wn + nj * 8 + c2;
                __nv_bfloat162 h01 = __floats2bfloat162_rn(a[0], a[1]);
                __nv_bfloat162 h23 = __floats2bfloat162_rn(a[2], a[3]);
                *reinterpret_cast<__nv_bfloat162*>(&Cb[(size_t)gr * DIM + gc]) = h01;
                *reinterpret_cast<__nv_bfloat162*>(&Cb[(size_t)(gr + 8) * DIM + gc]) = h23;
                if (bi != bj) {
                    Cb[(size_t)gc * DIM + gr]           = h01.x;
                    Cb[(size_t)(gc + 1) * DIM + gr]     = h01.y;
                    Cb[(size_t)gc * DIM + gr + 8]       = h23.x;
                    Cb[(size_t)(gc + 1) * DIM + gr + 8] = h23.y;
                }
            }
        }
    }
#pragma unroll
    for (int o = 16; o > 0; o >>= 1)
        fr += __shfl_xor_sync(0xffffffffu, fr, o);
    if (l == 0) sh_wsum[w] = fr;
    __syncthreads();
    if (tid == 0) {
        double tot = 0.0;
        for (int i = 0; i < 8; i++) tot += (double)sh_wsum[i];
        atomicAdd(&g_frob[z], tot);
        __threadfence();
        int tk = atomicAdd(&g_ctr[z], 1);
        if (tk == NTILE - 1) {
            g_ctr[z] = 0;
            __threadfence();
            double c = sqrt(g_frob[z]);
            g_inv[z] = (float)(1.0 / c);
            g_logacc[z] += log2(c) * wfin;
            g_frob[z] = 0.0;
        }
    }
}

// ===== Fused k=1 squaring (R11-proven: fp32 partial-sum loader, 2-stage) ====
__device__ __forceinline__ void sq_compute_stage(uint32_t u, float acc[4][4][4],
                                                 int wm, int wn, int g, int tr) {
#pragma unroll
    for (int kk = 0; kk < KCS; kk += 16) {
        uint32_t bh[2][4], ah[4][4];
        load_frags(u, kk, wm, wn, g, tr, ah, bh);
        mma_step(acc, ah, bh);
    }
}

__global__ void __launch_bounds__(256, 1)
sq_fused_kernel(int dst_sel, double wfin)
{
    extern __shared__ __align__(16) char dynsmem[];
    __shared__ float sh_wsum[8];

    const int z = blockIdx.z;
    const float* Af = g_part[0][z];
    __nv_bfloat16* Cb = g_hbuf[dst_sel][z];

    int t = blockIdx.x, bi = 0;
    while (t >= 8 - bi) { t -= 8 - bi; bi++; }
    const int bj = bi + t;
    const int i0 = bi * 128, j0 = bj * 128;

    const int tid = threadIdx.x;
    const int w = tid >> 5, l = tid & 31;
    const int wm = (w >> 2) * 64;
    const int wn = (w & 3) * 32;
    const int tr = l & 7, g = l >> 3;

    const float sv = g_inv[z];
    const float s2 = sv * sv;

    const uint32_t sb = smem_u32(dynsmem);
    const uint32_t ab = (sb + 1023u) & ~1023u;
    char* aptr = dynsmem + (ab - sb);

    float acc[4][4][4];
#pragma unroll
    for (int mi = 0; mi < 4; mi++)
#pragma unroll
        for (int nj = 0; nj < 4; nj++)
#pragma unroll
            for (int q = 0; q < 4; q++) acc[mi][nj][q] = 0.0f;

    const float* AIf = Af + i0 + 4 * l;
    const float* AJf = Af + j0 + 4 * l;
    const int lrow = w * 4;
    const int chunk = l >> 1;
    const int boff  = (l & 1) << 3;

    const int S = DIM / KCS;
    uint2 sI[4], sJ[4];

    auto loadf = [&](int kbase) {
#pragma unroll
        for (int rr = 0; rr < 4; rr++) {
            float4 v = ldp4(AIf + (size_t)(kbase + lrow + rr) * DIM);
            cvt_h(v, sI[rr]);
            v = ldp4(AJf + (size_t)(kbase + lrow + rr) * DIM);
            cvt_h(v, sJ[rr]);
        }
    };
    auto storef = [&](char* bufp) {
#pragma unroll
        for (int rr = 0; rr < 4; rr++) {
            const int k = lrow + rr;
            const uint32_t off = (uint32_t)(k * 256) + ((chunk ^ (k & 7)) << 4) + boff;
            *(uint2*)(bufp + off)         = sI[rr];
            *(uint2*)(bufp + SREGB + off) = sJ[rr];
        }
    };

    loadf(0);
    storef(aptr);
    loadf(KCS);
    __syncthreads();

    for (int s = 0; s < S; s++) {
        const int b = s & 1;
        if (s + 1 < S) storef(aptr + (b ^ 1) * SSTAGEB);
        if (s + 2 < S) loadf((s + 2) * KCS);
        sq_compute_stage(ab + b * SSTAGEB, acc, wm, wn, g, tr);
        __syncthreads();
    }

    sq_epilogue(acc, bi, bj, i0, j0, wm, wn, tid, w, l, s2, 1, wfin, Cb, z, sh_wsum);
}

// ===== k>=2 squaring: 4-stage cp.async pipeline, bf16 chain (R12-proven) ====
__global__ void __launch_bounds__(256, 1)
sq_cp_kernel(int src_sel, int dst_sel, int do_write, double wfin)
{
    extern __shared__ __align__(16) char dynsmem[];
    __shared__ float sh_wsum[8];

    const int z = blockIdx.z;
    const __nv_bfloat16* Ab = g_hbuf[src_sel][z];
    __nv_bfloat16* Cb = g_hbuf[dst_sel][z];

    int t = blockIdx.x, bi = 0;
    while (t >= 8 - bi) { t -= 8 - bi; bi++; }
    const int bj = bi + t;
    const int i0 = bi * 128, j0 = bj * 128;

    const int tid = threadIdx.x;
    const int w = tid >> 5, l = tid & 31;
    const int wm = (w >> 2) * 64;
    const int wn = (w & 3) * 32;
    const int tr = l & 7, g = l >> 3;
    const int row = tid >> 3;
    const int cb  = (tid & 7) * 2;

    const float sv = g_inv[z];
    const float s2 = sv * sv;

    const uint32_t sb = smem_u32(dynsmem);

    float acc[4][4][4];
#pragma unroll
    for (int mi = 0; mi < 4; mi++)
#pragma unroll
        for (int nj = 0; nj < 4; nj++)
#pragma unroll
            for (int q = 0; q < 4; q++) acc[mi][nj][q] = 0.0f;

    const __nv_bfloat16* baseI = Ab + i0;
    const __nv_bfloat16* baseJ = Ab + j0;

    const int S = DIM / KCS;

    auto issue_stage = [&](int s) {
        const uint32_t bufb = sb + (uint32_t)(s & (NSTG - 1)) * SSTAGEB;
        const size_t krow = (size_t)(s * KCS + row) * DIM;
#pragma unroll
        for (int cc = 0; cc < 2; cc++) {
            const int ch = cb + cc;
            const uint32_t off = (uint32_t)(row * 256) + ((ch ^ (row & 7)) << 4);
            CP_ASYNC16(bufb + off,         baseI + krow + ch * 8);
            CP_ASYNC16(bufb + SREGB + off, baseJ + krow + ch * 8);
        }
    };

    issue_stage(0); CP_COMMIT();
    issue_stage(1); CP_COMMIT();
    issue_stage(2); CP_COMMIT();

    for (int s = 0; s < S; s++) {
        CP_WAIT2();
        __syncthreads();
        if (s + 3 < S) issue_stage(s + 3);
        CP_COMMIT();
        const uint32_t u = sb + (uint32_t)(s & (NSTG - 1)) * SSTAGEB;
        uint32_t ah[2][4][4], bh[2][2][4];
        load_frags(u, 0, wm, wn, g, tr, ah[0], bh[0]);
#pragma unroll
        for (int kk = 0; kk < KCS; kk += 16) {
            const int cu = (kk >> 4) & 1;
            if (kk + 16 < KCS)
                load_frags(u, kk + 16, wm, wn, g, tr, ah[cu ^ 1], bh[cu ^ 1]);
            mma_step(acc, ah[cu], bh[cu]);
        }
    }
    __syncthreads();

    sq_epilogue(acc, bi, bj, i0, j0, wm, wn, tid, w, l, s2, do_write, wfin,
                Cb, z, sh_wsum);
}

__global__ void out_kernel(float* __restrict__ out) {
    double l0 = exp2(g_logacc[0]);
    double l1 = exp2(g_logacc[1]);
    double l2 = exp2(g_logacc[2]);
    out[0] = (float)(l0 + 0.5 * (l1 + l2));
}

extern "C" void kernel_launch(void* const* d_in, const int* in_sizes, int n_in,
                              void* d_out, int out_size)
{
    const float* f1 = (const float*)d_in[0];
    const float* f2 = (const float*)d_in[1];
    const float* f3 = (const float*)d_in[2];
    (void)in_sizes; (void)n_in; (void)out_size;

    static int configured = 0;
    if (!configured) {
        cudaFuncSetAttribute(gram_cp_kernel,
                             cudaFuncAttributeMaxDynamicSharedMemorySize, CSMEMB);
        cudaFuncSetAttribute(sq_fused_kernel,
                             cudaFuncAttributeMaxDynamicSharedMemorySize, SSMEMB);
        cudaFuncSetAttribute(sq_cp_kernel,
                             cudaFuncAttributeMaxDynamicSharedMemorySize, CSMEMB);
        configured = 1;
    }

    init_kernel<<<1, 4>>>();

    // F -> bf16 (numerically identical to the old in-loader conversion)
    cvt_kernel<<<dim3(192, 3), 256>>>(f1, f2, f3);

    // Gram: 4-way K-split into fp32 partial planes, cp.async bf16 GEMM
    gram_cp_kernel<<<dim3(NTILE, KSPLIT, 3), 256, CSMEMB>>>();

    // k=1: fused partial-sum loader (fp32), writes bf16 -> hbuf[0]
    sq_fused_kernel<<<dim3(NTILE, 1, 3), 256, SSMEMB>>>(0, exp2(-1.0));
    int cur = 0;
    for (int k = 2; k <= M_SQ; k++) {
        int dst = 1 - cur;
        int dow = (k < M_SQ) ? 1 : 0;
        sq_cp_kernel<<<dim3(NTILE, 1, 3), 256, CSMEMB>>>(
            cur, dst, dow, exp2(-(double)k));
        cur = dst;
    }
    out_kernel<<<1, 1>>>((float*)d_out);
}